// round 1
// baseline (speedup 1.0000x reference)
#include <cuda_runtime.h>
#include <math_constants.h>
#include <cstdint>

// Scratch (no allocations allowed): partial (m, l, ctx[32]) per (b, chunk),
// plus final (M, 1/L) per b for the weight-normalization pass.
__device__ float g_pm[8192];
__device__ float g_pl[8192];
__device__ float g_pctx[8192 * 32];
__device__ float g_M[2048];
__device__ float g_invL[2048];

// ---------------------------------------------------------------------------
// Kernel 1: fused keys-GEMM + tanh-score + online-softmax + context partials.
// Grid: (S/1024 chunks, B). Block: 256 threads (8 warps).
// Each lane owns one row s: computes key[0..32) in registers via f32x2 FMA
// against Wk broadcast from shared, then score, then online (m,l,ctx) update.
// Raw scores are written to the att_weights output region (normalized later).
// ---------------------------------------------------------------------------
__global__ __launch_bounds__(256)
void attn_main(const float* __restrict__ lstm, const float* __restrict__ fh,
               const float* __restrict__ Wq, const float* __restrict__ bq,
               const float* __restrict__ Wk, const float* __restrict__ bk,
               const float* __restrict__ Wv, const float* __restrict__ bv,
               float* __restrict__ out_scores, int S)
{
    const int b     = blockIdx.y;
    const int chunk = blockIdx.x;
    const int nCh   = gridDim.x;
    const int tid   = threadIdx.x;
    const int w     = tid >> 5;
    const int lane  = tid & 31;

    __shared__ __align__(16) float sWk[1024];   // Wk[h][d], row-major (as given)
    __shared__ __align__(16) float sBk[32];
    __shared__ float2 sQW[32];                  // {query[d], Wv[d]}
    __shared__ float  sRed[8 * 32];
    __shared__ float  sMw[8], sLw[8];
    __shared__ float  sBv;

    for (int i = tid; i < 1024; i += 256) sWk[i] = Wk[i];
    if (tid < 32) {
        sBk[tid] = bk[tid];
        float acc = bq[tid];
        #pragma unroll 1
        for (int h = 0; h < 32; ++h) acc += fh[b * 32 + h] * Wq[h * 32 + tid];
        sQW[tid] = make_float2(acc, Wv[tid]);
    }
    if (tid == 0) sBv = bv[0];
    __syncthreads();

    const float bv0 = sBv;
    float m = -CUDART_INF_F, l = 0.f;
    float ctx[32];
    #pragma unroll
    for (int d = 0; d < 32; ++d) ctx[d] = 0.f;

    const ulonglong2* sWk2 = reinterpret_cast<const ulonglong2*>(sWk);
    const ulonglong2* sBk2 = reinterpret_cast<const ulonglong2*>(sBk);

    #pragma unroll 1
    for (int it = 0; it < 4; ++it) {
        const int s = chunk * 1024 + w * 128 + it * 32 + lane;
        if (s >= S) continue;

        const float4* xrow =
            reinterpret_cast<const float4*>(lstm + ((size_t)b * S + s) * 32);

        // acc2: 16 f32x2 accumulators = key[0..32), initialized to bk
        unsigned long long acc2[16];
        #pragma unroll
        for (int j = 0; j < 8; ++j) {
            ulonglong2 bb = sBk2[j];
            acc2[2 * j] = bb.x; acc2[2 * j + 1] = bb.y;
        }

        #pragma unroll 1
        for (int jx = 0; jx < 8; ++jx) {
            float4 xq = __ldg(xrow + jx);
            float xs[4] = {xq.x, xq.y, xq.z, xq.w};
            #pragma unroll
            for (int i = 0; i < 4; ++i) {
                unsigned long long aa;
                asm("mov.b64 %0, {%1, %1};" : "=l"(aa) : "f"(xs[i]));
                const int hp = jx * 4 + i;
                #pragma unroll
                for (int j2 = 0; j2 < 8; ++j2) {
                    ulonglong2 wv2 = sWk2[hp * 8 + j2];   // broadcast LDS.128
                    asm("fma.rn.f32x2 %0, %1, %2, %0;"
                        : "+l"(acc2[2 * j2]) : "l"(aa), "l"(wv2.x));
                    asm("fma.rn.f32x2 %0, %1, %2, %0;"
                        : "+l"(acc2[2 * j2 + 1]) : "l"(aa), "l"(wv2.y));
                }
            }
        }

        float key[32];
        #pragma unroll
        for (int p = 0; p < 16; ++p)
            asm("mov.b64 {%0, %1}, %2;"
                : "=f"(key[2 * p]), "=f"(key[2 * p + 1]) : "l"(acc2[p]));

        float score = bv0;
        #pragma unroll
        for (int d = 0; d < 32; ++d) {
            float2 qw = sQW[d];
            float z = key[d] + qw.x;
            float e = __expf(2.f * z);        // inf/0 at extremes -> t = +/-1, correct
            float r;
            asm("rcp.approx.f32 %0, %1;" : "=f"(r) : "f"(e + 1.f));
            float t = fmaf(-2.f, r, 1.f);     // tanh(z)
            score = fmaf(t, qw.y, score);
        }

        out_scores[(size_t)b * S + s] = score;  // raw score; kernel 3 normalizes

        float m_new = fmaxf(m, score);
        float c = __expf(m - m_new);            // 0 when m == -inf
        float p = __expf(score - m_new);
        l = fmaf(l, c, p);
        #pragma unroll
        for (int d = 0; d < 32; ++d) ctx[d] = fmaf(ctx[d], c, p * key[d]);
        m = m_new;
    }

    // ---- CTA reduction of (m, l, ctx[32]) ----
    float wm = m;
    #pragma unroll
    for (int off = 16; off; off >>= 1)
        wm = fmaxf(wm, __shfl_xor_sync(0xffffffffu, wm, off));
    if (lane == 0) sMw[w] = wm;
    __syncthreads();
    float Mcta = sMw[0];
    #pragma unroll
    for (int ww = 1; ww < 8; ++ww) Mcta = fmaxf(Mcta, sMw[ww]);

    float scale = __expf(m - Mcta);
    float lp = l * scale;
    #pragma unroll
    for (int d = 0; d < 32; ++d) ctx[d] *= scale;

    #pragma unroll
    for (int off = 16; off; off >>= 1) {
        lp += __shfl_xor_sync(0xffffffffu, lp, off);
        #pragma unroll
        for (int d = 0; d < 32; ++d)
            ctx[d] += __shfl_xor_sync(0xffffffffu, ctx[d], off);
    }
    if (lane == 0) {
        sLw[w] = lp;
        #pragma unroll
        for (int d = 0; d < 32; ++d) sRed[w * 32 + d] = ctx[d];
    }
    __syncthreads();

    if (tid < 32) {
        float cs = 0.f;
        #pragma unroll
        for (int ww = 0; ww < 8; ++ww) cs += sRed[ww * 32 + tid];
        const int pc = b * nCh + chunk;
        g_pctx[pc * 32 + tid] = cs;
        if (tid == 0) {
            float ls = 0.f;
            #pragma unroll
            for (int ww = 0; ww < 8; ++ww) ls += sLw[ww];
            g_pm[pc] = Mcta;
            g_pl[pc] = ls;
        }
    }
}

// ---------------------------------------------------------------------------
// Kernel 2: merge per-chunk partials per batch -> context output + (M, 1/L).
// ---------------------------------------------------------------------------
__global__ void attn_combine(float* __restrict__ out_ctx, int nCh)
{
    const int b = blockIdx.x;
    const int d = threadIdx.x;

    float M = -CUDART_INF_F;
    for (int c = 0; c < nCh; ++c) M = fmaxf(M, g_pm[b * nCh + c]);

    float L = 0.f, cs = 0.f;
    for (int c = 0; c < nCh; ++c) {
        float sc = __expf(g_pm[b * nCh + c] - M);
        L  += g_pl[b * nCh + c] * sc;
        cs += g_pctx[(b * nCh + c) * 32 + d] * sc;
    }
    float invL = 1.f / L;
    out_ctx[b * 32 + d] = cs * invL;
    if (d == 0) { g_M[b] = M; g_invL[b] = invL; }
}

// ---------------------------------------------------------------------------
// Kernel 3: normalize raw scores in-place into softmax weights.
// ---------------------------------------------------------------------------
__global__ void attn_norm(float* __restrict__ wout, int S, int n)
{
    const int i = blockIdx.x * blockDim.x + threadIdx.x;
    if (i < n) {
        const int b = i / S;
        wout[i] = __expf(wout[i] - g_M[b]) * g_invL[b];
    }
}

// ---------------------------------------------------------------------------
extern "C" void kernel_launch(void* const* d_in, const int* in_sizes, int n_in,
                              void* d_out, int out_size)
{
    const float* lstm = (const float*)d_in[0];
    const float* fh   = (const float*)d_in[1];
    const float* Wq   = (const float*)d_in[2];
    const float* bq   = (const float*)d_in[3];
    const float* Wk   = (const float*)d_in[4];
    const float* bk   = (const float*)d_in[5];
    const float* Wv   = (const float*)d_in[6];
    const float* bv   = (const float*)d_in[7];

    const int BH = in_sizes[1];          // B * H
    const int B  = BH / 32;
    const int S  = in_sizes[0] / BH;
    const int nCh = (S + 1023) / 1024;

    float* out_ctx = (float*)d_out;                    // [B, 32]
    float* scores  = out_ctx + (size_t)B * 32;         // [B, S] (weights region)

    dim3 grid(nCh, B);
    attn_main<<<grid, 256>>>(lstm, fh, Wq, bq, Wk, bk, Wv, bv, scores, S);
    attn_combine<<<B, 32>>>(out_ctx, nCh);

    const int n = B * S;
    attn_norm<<<(n + 255) / 256, 256>>>(scores, S, n);
}

// round 2
// speedup vs baseline: 1.5358x; 1.5358x over previous
#include <cuda_runtime.h>
#include <math_constants.h>
#include <cstdint>

// Scratch (no allocations allowed).
__device__ float g_pm[8192];
__device__ float g_pl[8192];
__device__ float g_pctx[8192 * 32];
__device__ float g_M[2048];
__device__ float g_invL[2048];

#define FMA2(acc, a, w) \
    asm("fma.rn.f32x2 %0, %1, %2, %0;" : "+l"(acc) : "l"(a), "l"(w))
#define DUP2(dst, s) \
    asm("mov.b64 %0, {%1, %1};" : "=l"(dst) : "f"(s))
#define ADD2(dst, a, b) \
    asm("add.rn.f32x2 %0, %1, %2;" : "=l"(dst) : "l"(a), "l"(b))
#define MUL2(dst, a, b) \
    asm("mul.rn.f32x2 %0, %1, %2;" : "=l"(dst) : "l"(a), "l"(b))
#define UNPK2(lo, hi, s) \
    asm("mov.b64 {%0, %1}, %2;" : "=f"(lo), "=f"(hi) : "l"(s))

// ---------------------------------------------------------------------------
// Kernel 1: fused keys-GEMM + tanh-score + online-softmax + context partials.
// Grid (S/1024, B), 256 threads. Lane owns a row; rows staged through smem
// with coalesced LDG + XOR-swizzled LDS (conflict-free per 8-lane phase).
// ---------------------------------------------------------------------------
__global__ __launch_bounds__(256, 2)
void attn_main(const float* __restrict__ lstm, const float* __restrict__ fh,
               const float* __restrict__ Wq, const float* __restrict__ bq,
               const float* __restrict__ Wk, const float* __restrict__ bk,
               const float* __restrict__ Wv, const float* __restrict__ bv,
               float* __restrict__ out_scores, int S)
{
    const int b     = blockIdx.y;
    const int chunk = blockIdx.x;
    const int nCh   = gridDim.x;
    const int tid   = threadIdx.x;
    const int w     = tid >> 5;
    const int lane  = tid & 31;

    __shared__ __align__(16) float sWk[1024];     // Wk[h][d] row-major
    __shared__ __align__(16) float sX[8 * 1024];  // per-warp 32-row stage (swizzled)
    __shared__ __align__(16) float sQ[32];
    __shared__ __align__(16) float sBk[32];
    __shared__ float sWv[32];
    __shared__ float sRed[8 * 32], sMw[8], sLw[8], sBv;

    ((float4*)sWk)[tid] = ((const float4*)Wk)[tid];   // 256 f4 = 1024 floats
    if (tid < 32) {
        sBk[tid] = bk[tid];
        sWv[tid] = Wv[tid];
        float acc = bq[tid];
        #pragma unroll
        for (int h = 0; h < 32; ++h)
            acc = fmaf(fh[b * 32 + h], Wq[h * 32 + tid], acc);
        sQ[tid] = acc;
    }
    if (tid == 0) sBv = bv[0];
    __syncthreads();

    const float bv0 = sBv;
    float m = -CUDART_INF_F, l = 0.f;
    unsigned long long ctx2[16];
    #pragma unroll
    for (int j = 0; j < 16; ++j) ctx2[j] = 0ull;

    float4* xbuf = (float4*)(sX + w * 1024);          // 32 rows x 8 float4
    const ulonglong2* sWkq = (const ulonglong2*)sWk;
    const ulonglong2* sBk2 = (const ulonglong2*)sBk;
    const unsigned long long* sQ2 = (const unsigned long long*)sQ;

    unsigned long long Cdup;                          // 2*log2(e)
    DUP2(Cdup, 2.8853900817779268f);

    #pragma unroll 1
    for (int it = 0; it < 4; ++it) {
        const int gs = chunk * 1024 + w * 128 + it * 32;
        if (gs >= S) continue;
        const bool valid = (gs + lane) < S;

        // ---- stage 32 rows (4 KB, contiguous) coalesced, MLP=8 ----
        const float4* gsrc = (const float4*)lstm + ((size_t)b * S + gs) * 8;
        const int maxIdx = (S - gs) * 8 - 1;          // clamp for tail
        float4 v[8];
        __syncwarp();
        #pragma unroll
        for (int k = 0; k < 8; ++k)
            v[k] = gsrc[min(k * 32 + lane, maxIdx)];
        #pragma unroll
        for (int k = 0; k < 8; ++k) {
            int idx = k * 32 + lane;
            int row = idx >> 3, c = idx & 7;
            xbuf[row * 8 + (c ^ (row & 7))] = v[k];
        }
        __syncwarp();

        // ---- keys GEMM: key[0..32) in 16 packed accumulators ----
        unsigned long long acc2[16];
        #pragma unroll
        for (int j = 0; j < 8; ++j) {
            ulonglong2 t = sBk2[j];
            acc2[2 * j] = t.x; acc2[2 * j + 1] = t.y;
        }
        #pragma unroll
        for (int jx = 0; jx < 8; ++jx) {
            float4 xq = xbuf[lane * 8 + (jx ^ (lane & 7))];
            float xs[4] = {xq.x, xq.y, xq.z, xq.w};
            #pragma unroll
            for (int i = 0; i < 4; ++i) {
                unsigned long long aa;
                DUP2(aa, xs[i]);
                const int h = jx * 4 + i;
                #pragma unroll
                for (int j2 = 0; j2 < 8; ++j2) {
                    ulonglong2 w2 = sWkq[h * 8 + j2];  // broadcast LDS.128
                    FMA2(acc2[2 * j2],     aa, w2.x);
                    FMA2(acc2[2 * j2 + 1], aa, w2.y);
                }
            }
        }

        // ---- score = bv + sum_d tanh(key_d + q_d) * wv_d ----
        float sA = 0.f, sB = 0.f, sC = 0.f, sD = 0.f;
        #pragma unroll
        for (int j = 0; j < 16; ++j) {
            unsigned long long z2, a2;
            ADD2(z2, acc2[j], sQ2[j]);
            MUL2(a2, z2, Cdup);                        // 2*z*log2e
            float a0, a1;
            UNPK2(a0, a1, a2);
            float e0, e1;
            asm("ex2.approx.f32 %0, %1;" : "=f"(e0) : "f"(a0));
            asm("ex2.approx.f32 %0, %1;" : "=f"(e1) : "f"(a1));
            float r0, r1;
            asm("rcp.approx.f32 %0, %1;" : "=f"(r0) : "f"(e0 + 1.f));
            asm("rcp.approx.f32 %0, %1;" : "=f"(r1) : "f"(e1 + 1.f));
            float t0 = fmaf(-2.f, r0, 1.f);
            float t1 = fmaf(-2.f, r1, 1.f);
            if (j & 1) { sC = fmaf(t0, sWv[2 * j], sC); sD = fmaf(t1, sWv[2 * j + 1], sD); }
            else       { sA = fmaf(t0, sWv[2 * j], sA); sB = fmaf(t1, sWv[2 * j + 1], sB); }
        }
        const float score = bv0 + ((sA + sB) + (sC + sD));

        if (valid) {
            out_scores[(size_t)b * S + gs + lane] = score;  // coalesced raw store
            const float m_new = fmaxf(m, score);
            const float c = __expf(m - m_new);   // m=-inf first pass -> 0, ok
            const float p = __expf(score - m_new);
            l = fmaf(l, c, p);
            unsigned long long c2, p2;
            DUP2(c2, c); DUP2(p2, p);
            #pragma unroll
            for (int j = 0; j < 16; ++j) {
                unsigned long long t;
                MUL2(t, acc2[j], p2);
                asm("fma.rn.f32x2 %0, %0, %1, %2;" : "+l"(ctx2[j]) : "l"(c2), "l"(t));
            }
            m = m_new;
        }
    }

    // ---- CTA reduction of (m, l, ctx[32]) ----
    float ctx[32];
    #pragma unroll
    for (int j = 0; j < 16; ++j) UNPK2(ctx[2 * j], ctx[2 * j + 1], ctx2[j]);

    float wm = m;
    #pragma unroll
    for (int off = 16; off; off >>= 1)
        wm = fmaxf(wm, __shfl_xor_sync(0xffffffffu, wm, off));
    if (lane == 0) sMw[w] = wm;
    __syncthreads();
    float Mcta = sMw[0];
    #pragma unroll
    for (int ww = 1; ww < 8; ++ww) Mcta = fmaxf(Mcta, sMw[ww]);

    const float scale = (m > -CUDART_INF_F) ? __expf(m - Mcta) : 0.f;
    float lp = l * scale;
    #pragma unroll
    for (int d = 0; d < 32; ++d) ctx[d] *= scale;

    #pragma unroll
    for (int off = 16; off; off >>= 1) {
        lp += __shfl_xor_sync(0xffffffffu, lp, off);
        #pragma unroll
        for (int d = 0; d < 32; ++d)
            ctx[d] += __shfl_xor_sync(0xffffffffu, ctx[d], off);
    }
    if (lane == 0) {
        sLw[w] = lp;
        #pragma unroll
        for (int d = 0; d < 32; ++d) sRed[w * 32 + d] = ctx[d];
    }
    __syncthreads();

    if (tid < 32) {
        float cs = 0.f;
        #pragma unroll
        for (int ww = 0; ww < 8; ++ww) cs += sRed[ww * 32 + tid];
        const int pc = b * nCh + chunk;
        g_pctx[pc * 32 + tid] = cs;
        if (tid == 0) {
            float ls = 0.f;
            #pragma unroll
            for (int ww = 0; ww < 8; ++ww) ls += sLw[ww];
            g_pm[pc] = Mcta;
            g_pl[pc] = ls;
        }
    }
}

// ---------------------------------------------------------------------------
// Kernel 2: merge per-chunk partials per batch -> context output + (M, 1/L).
// ---------------------------------------------------------------------------
__global__ void attn_combine(float* __restrict__ out_ctx, int nCh)
{
    const int b = blockIdx.x;
    const int d = threadIdx.x;

    float M = -CUDART_INF_F;
    for (int c = 0; c < nCh; ++c) M = fmaxf(M, g_pm[b * nCh + c]);

    float L = 0.f, cs = 0.f;
    for (int c = 0; c < nCh; ++c) {
        float sc = __expf(g_pm[b * nCh + c] - M);
        L  += g_pl[b * nCh + c] * sc;
        cs += g_pctx[(b * nCh + c) * 32 + d] * sc;
    }
    float invL = 1.f / L;
    out_ctx[b * 32 + d] = cs * invL;
    if (d == 0) { g_M[b] = M; g_invL[b] = invL; }
}

// ---------------------------------------------------------------------------
// Kernel 3: normalize raw scores in-place into softmax weights.
// ---------------------------------------------------------------------------
__global__ void attn_norm(float* __restrict__ wout, int S)
{
    const int b = blockIdx.y;
    const int i = blockIdx.x * 256 + threadIdx.x;
    if (i < S)
        wout[(size_t)b * S + i] = __expf(wout[(size_t)b * S + i] - g_M[b]) * g_invL[b];
}

// ---------------------------------------------------------------------------
extern "C" void kernel_launch(void* const* d_in, const int* in_sizes, int n_in,
                              void* d_out, int out_size)
{
    const float* lstm = (const float*)d_in[0];
    const float* fh   = (const float*)d_in[1];
    const float* Wq   = (const float*)d_in[2];
    const float* bq   = (const float*)d_in[3];
    const float* Wk   = (const float*)d_in[4];
    const float* bk   = (const float*)d_in[5];
    const float* Wv   = (const float*)d_in[6];
    const float* bv   = (const float*)d_in[7];

    const int BH = in_sizes[1];           // B * H
    const int B  = BH / 32;
    const int S  = in_sizes[0] / BH;
    const int nCh = (S + 1023) / 1024;

    float* out_ctx = (float*)d_out;                 // [B, 32]
    float* scores  = out_ctx + (size_t)B * 32;      // [B, S]

    dim3 grid(nCh, B);
    attn_main<<<grid, 256>>>(lstm, fh, Wq, bq, Wk, bk, Wv, bv, scores, S);
    attn_combine<<<B, 32>>>(out_ctx, nCh);

    dim3 ngrid((S + 255) / 256, B);
    attn_norm<<<ngrid, 256>>>(scores, S);
}

// round 3
// speedup vs baseline: 1.7436x; 1.1353x over previous
#include <cuda_runtime.h>
#include <math_constants.h>
#include <cstdint>

// Scratch (no allocations allowed).
__device__ float g_pm[8192];
__device__ float g_pl[8192];
__device__ float g_pctx[8192 * 32];
__device__ float g_M[2048];
__device__ float g_invL[2048];

#define FMA2(acc, a, w) \
    asm("fma.rn.f32x2 %0, %1, %2, %0;" : "+l"(acc) : "l"(a), "l"(w))
#define FMA2O(dst, a, b_, c_) \
    asm("fma.rn.f32x2 %0, %1, %2, %3;" : "=l"(dst) : "l"(a), "l"(b_), "l"(c_))
#define DUP2(dst, s) \
    asm("mov.b64 %0, {%1, %1};" : "=l"(dst) : "f"(s))
#define MUL2(dst, a, b_) \
    asm("mul.rn.f32x2 %0, %1, %2;" : "=l"(dst) : "l"(a), "l"(b_))
#define UNPK2(lo, hi, s) \
    asm("mov.b64 {%0, %1}, %2;" : "=f"(lo), "=f"(hi) : "l"(s))

// ---------------------------------------------------------------------------
// Kernel 1: fused keys-GEMM + tanh-score + online-softmax + context partials.
// Grid (S/1024, B), 256 threads. Each lane owns TWO rows (lane, lane+32) of a
// 64-row warp group so every broadcast LDS.128 of Wk feeds 4 FFMA2.
// Dynamic smem: sWk[1024] + per-warp 64-row stage (8 KB, XOR-swizzled).
// ---------------------------------------------------------------------------
__global__ __launch_bounds__(256, 2)
void attn_main(const float* __restrict__ lstm, const float* __restrict__ fh,
               const float* __restrict__ Wq, const float* __restrict__ bq,
               const float* __restrict__ Wk, const float* __restrict__ bk,
               const float* __restrict__ Wv, const float* __restrict__ bv,
               float* __restrict__ out_scores, int S)
{
    const int b     = blockIdx.y;
    const int chunk = blockIdx.x;
    const int nCh   = gridDim.x;
    const int tid   = threadIdx.x;
    const int w     = tid >> 5;
    const int lane  = tid & 31;

    extern __shared__ __align__(16) float dyn[];
    float* sWk = dyn;                      // 1024 floats
    float* sX  = dyn + 1024;               // 8 warps * 2048 floats (64 rows)

    __shared__ __align__(16) float sQC[32];   // q[d] * 2log2e
    __shared__ __align__(16) float sBk[32];
    __shared__ float sNW[32];                 // -2 * wv[d]
    __shared__ float sRed[8 * 32], sMw[8], sLw[8], sW1;

    ((float4*)sWk)[tid] = ((const float4*)Wk)[tid];
    if (tid < 32) {
        sBk[tid] = bk[tid];
        const float wv = Wv[tid];
        sNW[tid] = -2.f * wv;
        float acc = bq[tid];
        #pragma unroll
        for (int h = 0; h < 32; ++h)
            acc = fmaf(fh[b * 32 + h], Wq[h * 32 + tid], acc);
        sQC[tid] = acc * 2.8853900817779268f;   // 2*log2(e)
        // sW1 = bv + sum_d wv[d]
        float t = wv;
        #pragma unroll
        for (int off = 16; off; off >>= 1)
            t += __shfl_xor_sync(0xffffffffu, t, off);
        if (tid == 0) sW1 = bv[0] + t;
    }
    __syncthreads();

    const float w1 = sW1;
    float m = -CUDART_INF_F, l = 0.f;
    unsigned long long ctx2[16];
    #pragma unroll
    for (int j = 0; j < 16; ++j) ctx2[j] = 0ull;

    float4* xbuf = (float4*)(sX + w * 2048);      // 64 rows x 8 float4
    const ulonglong2* sWkq = (const ulonglong2*)sWk;
    const ulonglong2* sBk2 = (const ulonglong2*)sBk;
    const unsigned long long* qc2 = (const unsigned long long*)sQC;

    unsigned long long Cdup;                       // 2*log2(e)
    DUP2(Cdup, 2.8853900817779268f);

    #pragma unroll 1
    for (int it = 0; it < 2; ++it) {
        const int gs = chunk * 1024 + w * 128 + it * 64;
        if (gs >= S) continue;

        // ---- stage 64 rows (8 KB) coalesced, two halves of MLP=8 ----
        const float4* gsrc = (const float4*)lstm + ((size_t)b * S + gs) * 8;
        const int maxIdx = (S - gs) * 8 - 1;
        __syncwarp();
        #pragma unroll 1
        for (int half = 0; half < 2; ++half) {
            float4 v[8];
            #pragma unroll
            for (int k = 0; k < 8; ++k)
                v[k] = gsrc[min(half * 256 + k * 32 + lane, maxIdx)];
            #pragma unroll
            for (int k = 0; k < 8; ++k) {
                int idx = half * 256 + k * 32 + lane;
                int row = idx >> 3, c = idx & 7;
                xbuf[row * 8 + (c ^ (row & 7))] = v[k];
            }
        }
        __syncwarp();

        // ---- keys GEMM: two rows per lane, 16 packed accs each ----
        unsigned long long acc[2][16];
        #pragma unroll
        for (int j = 0; j < 8; ++j) {
            ulonglong2 t = sBk2[j];
            acc[0][2 * j] = t.x; acc[0][2 * j + 1] = t.y;
            acc[1][2 * j] = t.x; acc[1][2 * j + 1] = t.y;
        }
        #pragma unroll
        for (int jx = 0; jx < 8; ++jx) {
            const int sw = jx ^ (lane & 7);
            float4 xqA = xbuf[lane * 8 + sw];
            float4 xqB = xbuf[(lane + 32) * 8 + sw];
            float xsA[4] = {xqA.x, xqA.y, xqA.z, xqA.w};
            float xsB[4] = {xqB.x, xqB.y, xqB.z, xqB.w};
            #pragma unroll
            for (int i = 0; i < 4; ++i) {
                unsigned long long aA, aB;
                DUP2(aA, xsA[i]);
                DUP2(aB, xsB[i]);
                const int h = jx * 4 + i;
                #pragma unroll
                for (int j2 = 0; j2 < 8; ++j2) {
                    ulonglong2 w2 = sWkq[h * 8 + j2];   // broadcast LDS.128
                    FMA2(acc[0][2 * j2],     aA, w2.x);
                    FMA2(acc[0][2 * j2 + 1], aA, w2.y);
                    FMA2(acc[1][2 * j2],     aB, w2.x);
                    FMA2(acc[1][2 * j2 + 1], aB, w2.y);
                }
            }
        }

        // ---- per-row: score + online-softmax + ctx update ----
        #pragma unroll
        for (int r = 0; r < 2; ++r) {
            const int srow = gs + r * 32 + lane;
            if (srow >= S) continue;

            // score = w1 + sum_d (-2*wv_d) * rcp(exp2((key+q)*2log2e) + 1)
            float s0 = 0.f, s1 = 0.f, s2 = 0.f, s3 = 0.f;
            #pragma unroll
            for (int j = 0; j < 16; ++j) {
                unsigned long long a2;
                FMA2O(a2, acc[r][j], Cdup, qc2[j]);
                float a0, a1;
                UNPK2(a0, a1, a2);
                float e0, e1;
                asm("ex2.approx.f32 %0, %1;" : "=f"(e0) : "f"(a0));
                asm("ex2.approx.f32 %0, %1;" : "=f"(e1) : "f"(a1));
                float r0, r1;
                asm("rcp.approx.f32 %0, %1;" : "=f"(r0) : "f"(e0 + 1.f));
                asm("rcp.approx.f32 %0, %1;" : "=f"(r1) : "f"(e1 + 1.f));
                if (j & 1) { s2 = fmaf(r0, sNW[2 * j], s2); s3 = fmaf(r1, sNW[2 * j + 1], s3); }
                else       { s0 = fmaf(r0, sNW[2 * j], s0); s1 = fmaf(r1, sNW[2 * j + 1], s1); }
            }
            const float score = w1 + ((s0 + s1) + (s2 + s3));

            out_scores[(size_t)b * S + srow] = score;   // raw, coalesced

            const float m_new = fmaxf(m, score);
            const float c = __expf(m - m_new);   // 0 on first pass (m=-inf)
            const float p = __expf(score - m_new);
            l = fmaf(l, c, p);
            unsigned long long c2, p2;
            DUP2(c2, c); DUP2(p2, p);
            #pragma unroll
            for (int j = 0; j < 16; ++j) {
                unsigned long long t;
                MUL2(t, acc[r][j], p2);
                asm("fma.rn.f32x2 %0, %0, %1, %2;" : "+l"(ctx2[j]) : "l"(c2), "l"(t));
            }
            m = m_new;
        }
    }

    // ---- CTA reduction of (m, l, ctx[32]) ----
    float ctx[32];
    #pragma unroll
    for (int j = 0; j < 16; ++j) UNPK2(ctx[2 * j], ctx[2 * j + 1], ctx2[j]);

    float wm = m;
    #pragma unroll
    for (int off = 16; off; off >>= 1)
        wm = fmaxf(wm, __shfl_xor_sync(0xffffffffu, wm, off));
    if (lane == 0) sMw[w] = wm;
    __syncthreads();
    float Mcta = sMw[0];
    #pragma unroll
    for (int ww = 1; ww < 8; ++ww) Mcta = fmaxf(Mcta, sMw[ww]);

    const float scale = (m > -CUDART_INF_F) ? __expf(m - Mcta) : 0.f;
    float lp = l * scale;
    #pragma unroll
    for (int d = 0; d < 32; ++d) ctx[d] *= scale;

    #pragma unroll
    for (int off = 16; off; off >>= 1) {
        lp += __shfl_xor_sync(0xffffffffu, lp, off);
        #pragma unroll
        for (int d = 0; d < 32; ++d)
            ctx[d] += __shfl_xor_sync(0xffffffffu, ctx[d], off);
    }
    if (lane == 0) {
        sLw[w] = lp;
        #pragma unroll
        for (int d = 0; d < 32; ++d) sRed[w * 32 + d] = ctx[d];
    }
    __syncthreads();

    if (tid < 32) {
        float cs = 0.f;
        #pragma unroll
        for (int ww = 0; ww < 8; ++ww) cs += sRed[ww * 32 + tid];
        const int pc = b * nCh + chunk;
        g_pctx[pc * 32 + tid] = cs;
        if (tid == 0) {
            float ls = 0.f;
            #pragma unroll
            for (int ww = 0; ww < 8; ++ww) ls += sLw[ww];
            g_pm[pc] = Mcta;
            g_pl[pc] = ls;
        }
    }
}

// ---------------------------------------------------------------------------
// Kernel 2: merge per-chunk partials per batch -> context output + (M, 1/L).
// ---------------------------------------------------------------------------
__global__ void attn_combine(float* __restrict__ out_ctx, int nCh)
{
    const int b = blockIdx.x;
    const int d = threadIdx.x;

    float M = -CUDART_INF_F;
    for (int c = 0; c < nCh; ++c) M = fmaxf(M, g_pm[b * nCh + c]);

    float L = 0.f, cs = 0.f;
    for (int c = 0; c < nCh; ++c) {
        float sc = __expf(g_pm[b * nCh + c] - M);
        L  += g_pl[b * nCh + c] * sc;
        cs += g_pctx[(b * nCh + c) * 32 + d] * sc;
    }
    float invL = 1.f / L;
    out_ctx[b * 32 + d] = cs * invL;
    if (d == 0) { g_M[b] = M; g_invL[b] = invL; }
}

// ---------------------------------------------------------------------------
// Kernel 3: normalize raw scores in-place into softmax weights.
// ---------------------------------------------------------------------------
__global__ void attn_norm(float* __restrict__ wout, int S)
{
    const int b = blockIdx.y;
    const int i = blockIdx.x * 256 + threadIdx.x;
    if (i < S)
        wout[(size_t)b * S + i] = __expf(wout[(size_t)b * S + i] - g_M[b]) * g_invL[b];
}

// ---------------------------------------------------------------------------
extern "C" void kernel_launch(void* const* d_in, const int* in_sizes, int n_in,
                              void* d_out, int out_size)
{
    const float* lstm = (const float*)d_in[0];
    const float* fh   = (const float*)d_in[1];
    const float* Wq   = (const float*)d_in[2];
    const float* bq   = (const float*)d_in[3];
    const float* Wk   = (const float*)d_in[4];
    const float* bk   = (const float*)d_in[5];
    const float* Wv   = (const float*)d_in[6];
    const float* bv   = (const float*)d_in[7];

    const int BH = in_sizes[1];           // B * H
    const int B  = BH / 32;
    const int S  = in_sizes[0] / BH;
    const int nCh = (S + 1023) / 1024;

    float* out_ctx = (float*)d_out;                 // [B, 32]
    float* scores  = out_ctx + (size_t)B * 32;      // [B, S]

    const int smemBytes = (1024 + 8 * 2048) * (int)sizeof(float);  // 69632
    static bool attrSet = false;
    if (!attrSet) {
        cudaFuncSetAttribute(attn_main,
                             cudaFuncAttributeMaxDynamicSharedMemorySize,
                             smemBytes);
        attrSet = true;
    }

    dim3 grid(nCh, B);
    attn_main<<<grid, 256, smemBytes>>>(lstm, fh, Wq, bq, Wk, bk, Wv, bv,
                                        scores, S);
    attn_combine<<<B, 32>>>(out_ctx, nCh);

    dim3 ngrid((S + 255) / 256, B);
    attn_norm<<<ngrid, 256>>>(scores, S);
}